// round 12
// baseline (speedup 1.0000x reference)
#include <cuda_runtime.h>
#include <cuda_fp16.h>
#include <cstdint>
#include <math.h>

#define NB 8
#define C 512
#define HO 64
#define PIX 4096
#define NT 72             // conv3: K tiles of 64

// ---------------- device scratch ------------------------------------------
__device__ __align__(128) __half g_xp[(size_t)NB * 33 * 33 * 512];
__device__ __align__(128) __half g_h1p[(size_t)NB * 66 * 66 * 512];
// fragment-layout fp16 weights: [mtile4][kt72][kg4][mf8][lane32][e8]
__device__ __align__(128) __half g_Ac2[(size_t)4 * 72 * 8192];
__device__ __align__(128) __half g_Au2[(size_t)4 * 72 * 8192];
__device__ float g_wsq_up[C * C];
__device__ float g_wsq_cT[C * C];
__device__ float g_s[3 * NB * C];
__device__ float g_sigma[2 * NB * C];

// subpixel class tables (ktile64 units)
__constant__ int c_T[9]  = {4, 3, 5, 1, 7, 0, 2, 6, 8};
__constant__ int c_OY[9] = {0, 0, 0, 1, 0, 1, 1, 0, 0};
__constant__ int c_OX[9] = {0, 1, 0, 0, 0, 1, 0, 1, 0};
__constant__ int c_KTB[4] = {0, 8, 24, 40};
__constant__ int c_NTC[4] = {8, 16, 16, 32};

__device__ __forceinline__ int pos16(int c) {
    return (c & ~15) | ((((c >> 1) & 3) << 2) | (((c >> 3) & 1) << 1) | (c & 1));
}

// ---------------- helpers --------------------------------------------------
__device__ __forceinline__ uint32_t smem_u32(const void* p) {
    uint32_t a;
    asm("{ .reg .u64 t; cvta.to.shared.u64 t, %1; cvt.u32.u64 %0, t; }" : "=r"(a) : "l"(p));
    return a;
}
__device__ __forceinline__ void cpa16(uint32_t s, const void* g) {
    asm volatile("cp.async.cg.shared.global [%0], [%1], 16;" :: "r"(s), "l"(g));
}
__device__ __forceinline__ void mma16(float* c, uint4 a, uint2 b) {
    asm volatile("mma.sync.aligned.m16n8k16.row.col.f32.f16.f16.f32 "
        "{%0,%1,%2,%3},{%4,%5,%6,%7},{%8,%9},{%0,%1,%2,%3};"
        : "+f"(c[0]), "+f"(c[1]), "+f"(c[2]), "+f"(c[3])
        : "r"(a.x), "r"(a.y), "r"(a.z), "r"(a.w), "r"(b.x), "r"(b.y));
}

// ---------------------------------------------------------------------------
// K0: weight-square tap sums
// ---------------------------------------------------------------------------
__global__ void k_wsq(const float* __restrict__ up_w, const float* __restrict__ c_w) {
    int idx = blockIdx.x * blockDim.x + threadIdx.x;
    int which = idx >> 18;
    int p = idx & 262143;
    int i = p >> 9, o = p & 511;
    const float* src = which == 0 ? (up_w + ((i << 9) + o) * 9)
                                  : (c_w + ((o << 9) + i) * 9);
    float s = 0.f;
#pragma unroll
    for (int t = 0; t < 9; t++) s += src[t] * src[t];
    if (which == 0) g_wsq_up[p] = s;
    else            g_wsq_cT[p] = s;
}

// ---------------------------------------------------------------------------
// K1: style vectors
// ---------------------------------------------------------------------------
__global__ void k_style(const float* __restrict__ v,
                        const float* __restrict__ up_sw, const float* __restrict__ up_sb,
                        const float* __restrict__ c_sw,  const float* __restrict__ c_sb,
                        const float* __restrict__ rgb_sw,const float* __restrict__ rgb_sb) {
    int m = blockIdx.y, n = blockIdx.x, i = threadIdx.x;
    __shared__ float sv[C];
    sv[i] = v[n * C + i];
    __syncthreads();
    const float* SW = (m == 0) ? up_sw : (m == 1) ? c_sw : rgb_sw;
    const float* SB = (m == 0) ? up_sb : (m == 1) ? c_sb : rgb_sb;
    float acc = SB[i];
#pragma unroll 4
    for (int l = 0; l < C; l++) acc = fmaf(sv[l], SW[l * C + i], acc);
    g_s[(m * NB + n) * C + i] = acc;
}

// ---------------------------------------------------------------------------
// K2: demod sigma
// ---------------------------------------------------------------------------
__global__ void k_sigma(void) {
    int m = blockIdx.y, n = blockIdx.x, o = threadIdx.x;
    __shared__ float s2[C];
    float sv = g_s[(m * NB + n) * C + o];
    s2[o] = sv * sv;
    __syncthreads();
    const float* wsq = (m == 0) ? g_wsq_up : g_wsq_cT;
    float acc = 1e-8f;
#pragma unroll 4
    for (int i = 0; i < C; i++) acc = fmaf(s2[i], wsq[i * C + o], acc);
    g_sigma[(m * NB + n) * C + o] = sqrtf(acc);
}

// ---------------------------------------------------------------------------
// K3: modulated x -> g_xp fp16 channels-last (per-16 k-perm), 33x33 pad
// ---------------------------------------------------------------------------
__global__ void k_modx(const float* __restrict__ x) {
    int idx = blockIdx.x * 256 + threadIdx.x;
    if (idx >= NB * 1089 * 128) return;
    int sub = idx & 3;
    int g = (idx >> 2) & 31;
    int cell = (idx >> 7) % 1089;
    int nn = (idx >> 7) / 1089;
    int yz = cell / 33, xz = cell % 33;
    __half2 lo = __floats2half2_rn(0.f, 0.f), hi = lo;
    if (yz < 32 && xz < 32) {
        int c0 = g * 16 + sub * 2;
        const float* sp = g_s + (0 * NB + nn) * C;
        const float* xp = x + (((size_t)nn * 512) * 32 + yz) * 32 + xz;
        lo = __floats2half2_rn(xp[(size_t)c0 * 1024] * sp[c0],
                               xp[(size_t)(c0 + 1) * 1024] * sp[c0 + 1]);
        hi = __floats2half2_rn(xp[(size_t)(c0 + 8) * 1024] * sp[c0 + 8],
                               xp[(size_t)(c0 + 9) * 1024] * sp[c0 + 9]);
    }
    __half2* dst = (__half2*)g_xp;
    dst[((size_t)(nn * 1089 + cell) * 512 + g * 16 + sub * 4) >> 1] = lo;
    dst[(((size_t)(nn * 1089 + cell) * 512 + g * 16 + sub * 4) >> 1) + 1] = hi;
}

// ---------------------------------------------------------------------------
// K3b: zero the halo of g_h1p
// ---------------------------------------------------------------------------
__global__ void k_halo(void) {
    int idx = blockIdx.x * 256 + threadIdx.x;
    if (idx >= NB * 260 * 64) return;
    int ci8 = idx & 63;
    int c2 = idx >> 6;
    int h = c2 % 260, nn = c2 / 260;
    int yz, xz;
    if (h < 66)       { yz = 0;  xz = h; }
    else if (h < 132) { yz = 65; xz = h - 66; }
    else { int rem = h - 132; yz = 1 + (rem >> 1); xz = (rem & 1) * 65; }
    ((uint4*)g_h1p)[((size_t)(nn * 66 + yz) * 66 + xz) * 64 + ci8] =
        make_uint4(0, 0, 0, 0);
}

// ---------------------------------------------------------------------------
// K3c: weights -> fp16 fragment layout
// ---------------------------------------------------------------------------
#define AFRAG_ELEMS 2359296
__global__ void k_prepA2(const float* __restrict__ up_w, const float* __restrict__ c_w) {
    int idx = blockIdx.x * 256 + threadIdx.x;
    int which = idx >= AFRAG_ELEMS;
    int off = which ? idx - AFRAG_ELEMS : idx;
    int e = off & 7, lane = (off >> 3) & 31;
    int mf = (off >> 8) & 7, kg = (off >> 11) & 3;
    int rest = off >> 13;
    int kt = rest % 72, mtile = rest / 72;
    int grp = lane >> 2, tig = lane & 3;
    int reg = e >> 1, h = e & 1;
    int m = mf * 16 + grp + (reg & 1) * 8;
    int klocal = tig * 2 + h + (reg >> 1) * 8;
    int oc = mtile * 128 + m;
    float w;
    if (which) {
        int tapidx = kt >> 3;
        int ci = (kt & 7) * 64 + kg * 16 + klocal;
        w = up_w[((size_t)ci * 512 + oc) * 9 + c_T[tapidx]];
    } else {
        int kglob = kt * 64 + kg * 16 + klocal;
        int t = kglob >> 9, ci = kglob & 511;
        w = c_w[((size_t)oc * 512 + ci) * 9 + t];
    }
    __half val = __float2half_rn(w);
    if (which) g_Au2[off] = val;
    else       g_Ac2[off] = val;
}

#define STAGE_BYTES 49152
#define NTHR 512

// fragment-double-buffered inner tile: prefetch kg+1 while issuing kg's MMAs
#define GEMM_TILE_BODY(stg)                                                     \
    do {                                                                        \
        const char* bW = (stg) + 16384 + (warpN * 64 + grp) * 32 + tig * 8;     \
        const char* aW = (stg) + (warpM * 2) * 512 + lane * 16;                 \
        uint2 bf[2][8];                                                         \
        uint4 af[2][2];                                                         \
        _Pragma("unroll")                                                       \
        for (int nf = 0; nf < 8; nf++) bf[0][nf] = *(const uint2*)(bW + nf * 256); \
        _Pragma("unroll")                                                       \
        for (int mf = 0; mf < 2; mf++) af[0][mf] = *(const uint4*)(aW + mf * 512); \
        _Pragma("unroll")                                                       \
        for (int kg = 0; kg < 4; kg++) {                                        \
            int cur = kg & 1, nxt = cur ^ 1;                                    \
            if (kg < 3) {                                                       \
                _Pragma("unroll")                                               \
                for (int nf = 0; nf < 8; nf++)                                  \
                    bf[nxt][nf] = *(const uint2*)(bW + (kg + 1) * 8192 + nf * 256); \
                _Pragma("unroll")                                               \
                for (int mf = 0; mf < 2; mf++)                                  \
                    af[nxt][mf] = *(const uint4*)(aW + (kg + 1) * 4096 + mf * 512); \
            }                                                                   \
            _Pragma("unroll")                                                   \
            for (int mf = 0; mf < 2; mf++)                                      \
                _Pragma("unroll")                                               \
                for (int nf = 0; nf < 8; nf++)                                  \
                    mma16(acc[mf][nf], af[cur][mf], bf[cur][nf]);               \
        }                                                                       \
    } while (0)

// ---------------------------------------------------------------------------
// K4a: upconv subpixel GEMM, fp16
// ---------------------------------------------------------------------------
__global__ void __launch_bounds__(NTHR)
k_gemmU(const float* __restrict__ bias_, const float* __restrict__ noise,
        const float* __restrict__ nsp) {
    extern __shared__ char sm[];
    const int tid = threadIdx.x;
    const int wid = tid >> 5, lane = tid & 31;
    const int warpM = wid >> 2, warpN = wid & 3;
    const int grp = lane >> 2, tig = lane & 3;

    const int mtile = blockIdx.x;
    const int ocb = mtile << 7;
    const int n_img = blockIdx.y >> 2;
    const int a0 = (blockIdx.y & 3) * 8;
    const int cls = blockIdx.z;
    const int dy = cls >> 1, dx = cls & 1;
    const int ktb = c_KTB[cls];
    const int NTc = c_NTC[cls];

    const char* Ablock = (const char*)g_Au2 + (size_t)mtile * 72 * 16384;
    const char* Bimg = (const char*)g_xp + (size_t)n_img * (33 * 33 * 512) * 2;
    const uint32_t sb = smem_u32(sm);

    uint32_t pixoff[4], soff[4];
#pragma unroll
    for (int it = 0; it < 4; it++) {
        int c = tid + NTHR * it;
        int nn = c >> 3, r = c & 7;
        int py = a0 + (nn >> 5), px = nn & 31;
        pixoff[it] = (uint32_t)(py * 33 + px) * 1024u + (uint32_t)r * 16u;
        soff[it] = (uint32_t)((r >> 1) * 8192 + nn * 32 + (r & 1) * 16);
    }

    float acc[2][8][4];
#pragma unroll
    for (int a = 0; a < 2; a++)
#pragma unroll
        for (int b = 0; b < 8; b++)
#pragma unroll
            for (int e = 0; e < 4; e++) acc[a][b][e] = 0.f;

    auto load_tile = [&](int ktl, int s) {
        int kt = ktb + ktl;
        uint32_t sa = sb + (uint32_t)s * STAGE_BYTES;
        const char* ag = Ablock + (size_t)kt * 16384;
#pragma unroll
        for (int it = 0; it < 2; it++)
            cpa16(sa + (uint32_t)(tid * 16 + it * 8192), ag + tid * 16 + it * 8192);
        int tapidx = kt >> 3, chunk = kt & 7;
        const char* bg = Bimg + (c_OY[tapidx] * 33 + c_OX[tapidx]) * 1024 + chunk * 128;
        uint32_t sbB = sa + 16384u;
#pragma unroll
        for (int it = 0; it < 4; it++)
            cpa16(sbB + soff[it], bg + pixoff[it]);
        asm volatile("cp.async.commit_group;" ::: "memory");
    };

    load_tile(0, 0);
    load_tile(1, 1);
    load_tile(2, 2);

#pragma unroll 1
    for (int kt = 0; kt < NTc; kt++) {
        if (kt < NTc - 2)       asm volatile("cp.async.wait_group 2;" ::: "memory");
        else if (kt == NTc - 2) asm volatile("cp.async.wait_group 1;" ::: "memory");
        else                    asm volatile("cp.async.wait_group 0;" ::: "memory");
        __syncthreads();
        if (kt + 3 < NTc) load_tile(kt + 3, (kt + 3) & 3);
        const char* stg = sm + (kt & 3) * STAGE_BYTES;
        GEMM_TILE_BODY(stg);
    }

    // ---------------- epilogue: scatter to parity class ----------------
    const float ns = nsp[0];
    __half* hb = g_h1p + (size_t)n_img * (66 * 66 * 512);
    const float* nzb = noise + (size_t)n_img * PIX;
#pragma unroll
    for (int mf = 0; mf < 2; mf++) {
#pragma unroll
        for (int h2 = 0; h2 < 2; h2++) {
            int oc = ocb + warpM * 32 + mf * 16 + grp + h2 * 8;
            float inv = 1.f / g_sigma[(0 * NB + n_img) * C + oc];
            float bias = bias_[oc];
            float sc = g_s[(1 * NB + n_img) * C + oc];
            int ocpos = pos16(oc);
#pragma unroll
            for (int nf = 0; nf < 8; nf++) {
                int pig = warpN * 64 + nf * 8 + 2 * tig;
                int a = a0 + (pig >> 5);
                int b = pig & 31;
                int y = 2 * a + dy;
                int x0 = 2 * b + dx, x1 = x0 + 2;
                float v0 = acc[mf][nf][h2 * 2 + 0] * inv + bias + ns * nzb[y * HO + x0];
                float v1 = acc[mf][nf][h2 * 2 + 1] * inv + bias + ns * nzb[y * HO + x1];
                v0 = v0 > 0.f ? v0 : 0.2f * v0;
                v1 = v1 > 0.f ? v1 : 0.2f * v1;
                hb[((size_t)(y + 1) * 66 + (x0 + 1)) * 512 + ocpos] = __float2half_rn(v0 * sc);
                hb[((size_t)(y + 1) * 66 + (x1 + 1)) * 512 + ocpos] = __float2half_rn(v1 * sc);
            }
        }
    }
}

// ---------------------------------------------------------------------------
// K4b: conv3 GEMM, fp16
// ---------------------------------------------------------------------------
__global__ void __launch_bounds__(NTHR)
k_gemmC(const float* __restrict__ bias_, const float* __restrict__ noise,
        const float* __restrict__ nsp, float* __restrict__ outp) {
    extern __shared__ char sm[];
    const int tid = threadIdx.x;
    const int wid = tid >> 5, lane = tid & 31;
    const int warpM = wid >> 2, warpN = wid & 3;
    const int grp = lane >> 2, tig = lane & 3;

    const int mtile = blockIdx.x;
    const int ocb = mtile << 7;
    const int n_img = blockIdx.y >> 4;
    const int blk = blockIdx.y & 15;
    const int pix0 = blk << 8;
    const int y0 = pix0 >> 6;

    const char* Ablock = (const char*)g_Ac2 + (size_t)mtile * 72 * 16384;
    const char* Bimg = (const char*)g_h1p + (size_t)n_img * (66 * 66 * 512) * 2;
    const uint32_t sb = smem_u32(sm);

    uint32_t pixoff[4], soff[4];
#pragma unroll
    for (int it = 0; it < 4; it++) {
        int c = tid + NTHR * it;
        int nn = c >> 3, r = c & 7;
        int py = y0 + (nn >> 6), px = nn & 63;
        pixoff[it] = (uint32_t)(py * 66 + px) * 1024u + (uint32_t)r * 16u;
        soff[it] = (uint32_t)((r >> 1) * 8192 + nn * 32 + (r & 1) * 16);
    }

    float acc[2][8][4];
#pragma unroll
    for (int a = 0; a < 2; a++)
#pragma unroll
        for (int b = 0; b < 8; b++)
#pragma unroll
            for (int e = 0; e < 4; e++) acc[a][b][e] = 0.f;

    auto load_tile = [&](int kt, int s) {
        uint32_t sa = sb + (uint32_t)s * STAGE_BYTES;
        const char* ag = Ablock + (size_t)kt * 16384;
#pragma unroll
        for (int it = 0; it < 2; it++)
            cpa16(sa + (uint32_t)(tid * 16 + it * 8192), ag + tid * 16 + it * 8192);
        int t = kt >> 3, chunk = kt & 7;
        int dy = t / 3, dx = t - dy * 3;
        const char* bg = Bimg + (dy * 66 + dx) * 1024 + chunk * 128;
        uint32_t sbB = sa + 16384u;
#pragma unroll
        for (int it = 0; it < 4; it++)
            cpa16(sbB + soff[it], bg + pixoff[it]);
        asm volatile("cp.async.commit_group;" ::: "memory");
    };

    load_tile(0, 0);
    load_tile(1, 1);
    load_tile(2, 2);

#pragma unroll 1
    for (int kt = 0; kt < NT; kt++) {
        if (kt < NT - 2)       asm volatile("cp.async.wait_group 2;" ::: "memory");
        else if (kt == NT - 2) asm volatile("cp.async.wait_group 1;" ::: "memory");
        else                   asm volatile("cp.async.wait_group 0;" ::: "memory");
        __syncthreads();
        if (kt + 3 < NT) load_tile(kt + 3, (kt + 3) & 3);
        const char* stg = sm + (kt & 3) * STAGE_BYTES;
        GEMM_TILE_BODY(stg);
    }

    const float ns = nsp[0];
#pragma unroll
    for (int mf = 0; mf < 2; mf++) {
#pragma unroll
        for (int h2 = 0; h2 < 2; h2++) {
            int oc = ocb + warpM * 32 + mf * 16 + grp + h2 * 8;
            float inv = 1.f / g_sigma[(1 * NB + n_img) * C + oc];
            float bias = bias_[oc];
#pragma unroll
            for (int nf = 0; nf < 8; nf++) {
                int pix = pix0 + warpN * 64 + nf * 8 + 2 * tig;
                float2 nz = *(const float2*)(noise + (size_t)n_img * PIX + pix);
                float v0 = acc[mf][nf][h2 * 2 + 0] * inv + bias + ns * nz.x;
                float v1 = acc[mf][nf][h2 * 2 + 1] * inv + bias + ns * nz.y;
                v0 = v0 > 0.f ? v0 : 0.2f * v0;
                v1 = v1 > 0.f ? v1 : 0.2f * v1;
                *(float2*)(outp + ((size_t)(n_img * 512 + oc) * PIX) + pix) =
                    make_float2(v0, v1);
            }
        }
    }
}

// ---------------------------------------------------------------------------
// K5: toRGB + lrelu + bilinear 2x skip add
// ---------------------------------------------------------------------------
__device__ __forceinline__ void bl_coords(int Y, int& k0, int& k1, float& w0, float& w1) {
    if (Y & 1) { k0 = (Y - 1) >> 1; k1 = k0 + 1 < 31 ? k0 + 1 : 31; w0 = 0.75f; w1 = 0.25f; }
    else       { int k = Y >> 1; k0 = k - 1 > 0 ? k - 1 : 0; k1 = k; w0 = 0.25f; w1 = 0.75f; }
}

__global__ void k_rgb(const float* __restrict__ yimg, const float* __restrict__ rgb_w,
                      const float* __restrict__ rgb_b, float* __restrict__ out) {
    __shared__ float sw3[3][C];
    const int n = blockIdx.y;
    const int tid = threadIdx.x;
    for (int e = tid; e < 3 * C; e += 256) {
        int c = e >> 9, ci = e & 511;
        sw3[c][ci] = rgb_w[c * C + ci] * g_s[(2 * NB + n) * C + ci];
    }
    __syncthreads();

    const int px = blockIdx.x * 1024 + tid * 4;
    const float* h2 = out + (size_t)n * C * PIX;
    float a0x = 0, a0y = 0, a0z = 0, a0w = 0;
    float a1x = 0, a1y = 0, a1z = 0, a1w = 0;
    float a2x = 0, a2y = 0, a2z = 0, a2w = 0;
#pragma unroll 4
    for (int ci = 0; ci < C; ci++) {
        float4 hv = *(const float4*)(h2 + (size_t)ci * PIX + px);
        float w0 = sw3[0][ci], w1 = sw3[1][ci], w2 = sw3[2][ci];
        a0x = fmaf(hv.x, w0, a0x); a0y = fmaf(hv.y, w0, a0y);
        a0z = fmaf(hv.z, w0, a0z); a0w = fmaf(hv.w, w0, a0w);
        a1x = fmaf(hv.x, w1, a1x); a1y = fmaf(hv.y, w1, a1y);
        a1z = fmaf(hv.z, w1, a1z); a1w = fmaf(hv.w, w1, a1w);
        a2x = fmaf(hv.x, w2, a2x); a2y = fmaf(hv.y, w2, a2y);
        a2z = fmaf(hv.z, w2, a2z); a2w = fmaf(hv.w, w2, a2w);
    }

    float accv[3][4] = {{a0x, a0y, a0z, a0w}, {a1x, a1y, a1z, a1w}, {a2x, a2y, a2z, a2w}};
    const int Y = px >> 6;
    const int X0 = px & 63;
    int ky0, ky1; float wy0, wy1;
    bl_coords(Y, ky0, ky1, wy0, wy1);
    const size_t IMG_OFF = (size_t)NB * C * PIX;

#pragma unroll
    for (int c = 0; c < 3; c++) {
        float bias = rgb_b[c];
        const float* yb = yimg + (size_t)(n * 3 + c) * 32 * 32;
#pragma unroll
        for (int k = 0; k < 4; k++) {
            float r = accv[c][k] + bias;
            r = r > 0.f ? r : 0.2f * r;
            int X = X0 + k;
            int kx0, kx1; float wx0, wx1;
            bl_coords(X, kx0, kx1, wx0, wx1);
            float bv = wy0 * (wx0 * yb[ky0 * 32 + kx0] + wx1 * yb[ky0 * 32 + kx1])
                     + wy1 * (wx0 * yb[ky1 * 32 + kx0] + wx1 * yb[ky1 * 32 + kx1]);
            out[IMG_OFF + (size_t)(n * 3 + c) * PIX + px + k] = bv + r;
        }
    }
}

// ---------------------------------------------------------------------------
extern "C" void kernel_launch(void* const* d_in, const int* in_sizes, int n_in,
                              void* d_out, int out_size) {
    const float* x       = (const float*)d_in[0];
    const float* v       = (const float*)d_in[1];
    const float* yimg    = (const float*)d_in[2];
    const float* noise1  = (const float*)d_in[3];
    const float* noise2  = (const float*)d_in[4];
    const float* up_w    = (const float*)d_in[5];
    const float* up_b    = (const float*)d_in[6];
    const float* up_sw   = (const float*)d_in[7];
    const float* up_sb   = (const float*)d_in[8];
    const float* c_w     = (const float*)d_in[9];
    const float* c_b     = (const float*)d_in[10];
    const float* c_sw    = (const float*)d_in[11];
    const float* c_sb    = (const float*)d_in[12];
    const float* rgb_w   = (const float*)d_in[13];
    const float* rgb_b   = (const float*)d_in[14];
    const float* rgb_sw  = (const float*)d_in[15];
    const float* rgb_sb  = (const float*)d_in[16];
    const float* nsp     = (const float*)d_in[17];
    float* out = (float*)d_out;

    const int SMEM_GEMM = 4 * STAGE_BYTES;   // 192KB
    cudaFuncSetAttribute(k_gemmU, cudaFuncAttributeMaxDynamicSharedMemorySize, SMEM_GEMM);
    cudaFuncSetAttribute(k_gemmC, cudaFuncAttributeMaxDynamicSharedMemorySize, SMEM_GEMM);

    k_style<<<dim3(NB, 3), C>>>(v, up_sw, up_sb, c_sw, c_sb, rgb_sw, rgb_sb);
    k_wsq<<<2048, 256>>>(up_w, c_w);
    k_sigma<<<dim3(NB, 2), C>>>();
    k_modx<<<4356, 256>>>(x);
    k_prepA2<<<18432, 256>>>(up_w, c_w);
    k_halo<<<520, 256>>>();
    k_gemmU<<<dim3(4, 32, 4), NTHR, SMEM_GEMM>>>(up_b, noise1, nsp);
    k_gemmC<<<dim3(4, 128), NTHR, SMEM_GEMM>>>(c_b, noise2, nsp, out);
    k_rgb<<<dim3(4, NB), 256>>>(yimg, rgb_w, rgb_b, out);
}